// round 8
// baseline (speedup 1.0000x reference)
#include <cuda_runtime.h>
#include <cstdint>

// Problem constants
#define Bb 32
#define Cc 64
#define Lc 8192
#define Mm (Bb * Lc)            // 262144 columns
#define NBLK 296                // 148 SMs x 2 resident blocks = single balanced wave
#define NT_G 2048               // gram tiles (128 cols each)
#define NT_A 2048               // apply tiles (128 cols each)
#define GPAD 132                // gram tile row stride (conflict-spreading pad)
#define EPSV 1e-5f

// ---------------- scratch (device globals; no allocation allowed) ----------------
__device__ __align__(16) float g_gram_part[NBLK * 4096];   // 4.85 MB partial Grams
__device__ __align__(16) float g_sum_part[NBLK * 64];
__device__ __align__(16) float g_gram[4096];
__device__ __align__(16) float g_mean[64];
__device__ __align__(16) float g_wmT[4096];                // wmT[k][c] = wm[c][k]
__device__ __align__(16) float g_bias[64];                 // wm @ mean

// ---------------- f32x2 helpers (FFMA2: 2x fp32 FMA throughput) ----------------
__device__ __forceinline__ unsigned long long dup2(float v) {
    unsigned long long r;
    asm("mov.b64 %0, {%1, %1};" : "=l"(r) : "f"(v));
    return r;
}
__device__ __forceinline__ void fma2(unsigned long long& d, unsigned long long a,
                                     unsigned long long b) {
    asm("fma.rn.f32x2 %0, %1, %2, %0;" : "+l"(d) : "l"(a), "l"(b));
}
__device__ __forceinline__ float2 unpk(unsigned long long v) {
    float2 r;
    asm("mov.b64 {%0, %1}, %2;" : "=f"(r.x), "=f"(r.y) : "l"(v));
    return r;
}
__device__ __forceinline__ uint32_t smem_u32(const void* p) {
    uint32_t a;
    asm("{ .reg .u64 t; cvta.to.shared.u64 t, %1; cvt.u32.u64 %0, t; }"
        : "=r"(a) : "l"(p));
    return a;
}
__device__ __forceinline__ void cpasync16(uint32_t dst, const float* src) {
    asm volatile("cp.async.cg.shared.global [%0], [%1], 16;" :: "r"(dst), "l"(src));
}
#define CP_COMMIT() asm volatile("cp.async.commit_group;" ::: "memory")
#define CP_WAIT(n)  asm volatile("cp.async.wait_group %0;" :: "n"(n) : "memory")

// ================= Kernel 1: per-block partial Gram + channel sums =================
// Grid 296. Each block accumulates a partial Gram over ~6.9 tiles of 64c x 128l
// (flat tile id: batch = tt>>6, l0 = (tt&63)*128), cp.async double-buffered.
// PAIR-OVER-L accumulators: acc[i][q] (f32x2) accumulates products for l-pairs;
// horizontal-summed once at the end. Both operands are direct vector LDS from
// the natural s[c][l] layout -> no transpose, no dup2 movs, no split-k.
// Thread (ty,tx) 16x16: rows r = ty*4..+3 (A broadcast), cols tx + 16q (B at
// row stride 132 -> 8 bank-group spread, 2 wf per LDS.128).
#define GRAM_SMEM (2 * 64 * GPAD * (int)sizeof(float))

__global__ __launch_bounds__(256, 2) void gram_kernel(const float* __restrict__ X) {
    extern __shared__ float gsm[];                      // 2 x [64][GPAD]
    const int tid = threadIdx.x;
    const int bid = blockIdx.x;
    const int ts = (bid * NT_G) / NBLK;
    const int te = ((bid + 1) * NT_G) / NBLK;

    const int ty = tid >> 4, tx = tid & 15;
    const int r = ty * 4;
    const uint32_t sbase = smem_u32(gsm);

    unsigned long long acc[4][4];
    #pragma unroll
    for (int i = 0; i < 4; i++) { acc[i][0] = acc[i][1] = acc[i][2] = acc[i][3] = 0ull; }
    float csum = 0.f;

    // ---- prefetch tile ts into buffer 0 ----
    {
        int bb = ts >> 6, l0 = (ts & 63) << 7;
        const float* Xb = X + (size_t)bb * (Cc * Lc) + l0;
        #pragma unroll
        for (int it = 0; it < 8; it++) {
            int p = it * 256 + tid, c = p >> 5, l4 = p & 31;
            cpasync16(sbase + (uint32_t)(c * GPAD + l4 * 4) * 4,
                      Xb + (size_t)c * Lc + l4 * 4);
        }
        CP_COMMIT();
    }

    #pragma unroll 1
    for (int i = ts; i < te; i++) {
        const int cur = (i - ts) & 1;
        if (i + 1 < te) {
            int bb = (i + 1) >> 6, l0 = ((i + 1) & 63) << 7;
            const float* Xb = X + (size_t)bb * (Cc * Lc) + l0;
            const uint32_t dst = sbase + (uint32_t)((1 - cur) * 64 * GPAD) * 4;
            #pragma unroll
            for (int it = 0; it < 8; it++) {
                int p = it * 256 + tid, c = p >> 5, l4 = p & 31;
                cpasync16(dst + (uint32_t)(c * GPAD + l4 * 4) * 4,
                          Xb + (size_t)c * Lc + l4 * 4);
            }
            CP_COMMIT();
            CP_WAIT(1);
        } else {
            CP_WAIT(0);
        }
        __syncthreads();

        const float* buf = gsm + cur * 64 * GPAD;
        #pragma unroll 4
        for (int l4 = 0; l4 < 32; l4++) {
            const float* bp = buf + l4 * 4;
            ulonglong2 a0 = *(const ulonglong2*)&bp[(r + 0) * GPAD];
            ulonglong2 a1 = *(const ulonglong2*)&bp[(r + 1) * GPAD];
            ulonglong2 a2 = *(const ulonglong2*)&bp[(r + 2) * GPAD];
            ulonglong2 a3 = *(const ulonglong2*)&bp[(r + 3) * GPAD];
            ulonglong2 b0 = *(const ulonglong2*)&bp[(tx     ) * GPAD];
            ulonglong2 b1 = *(const ulonglong2*)&bp[(tx + 16) * GPAD];
            ulonglong2 b2 = *(const ulonglong2*)&bp[(tx + 32) * GPAD];
            ulonglong2 b3 = *(const ulonglong2*)&bp[(tx + 48) * GPAD];
            // first l-pair of this float4
            fma2(acc[0][0], a0.x, b0.x); fma2(acc[0][1], a0.x, b1.x);
            fma2(acc[0][2], a0.x, b2.x); fma2(acc[0][3], a0.x, b3.x);
            fma2(acc[1][0], a1.x, b0.x); fma2(acc[1][1], a1.x, b1.x);
            fma2(acc[1][2], a1.x, b2.x); fma2(acc[1][3], a1.x, b3.x);
            fma2(acc[2][0], a2.x, b0.x); fma2(acc[2][1], a2.x, b1.x);
            fma2(acc[2][2], a2.x, b2.x); fma2(acc[2][3], a2.x, b3.x);
            fma2(acc[3][0], a3.x, b0.x); fma2(acc[3][1], a3.x, b1.x);
            fma2(acc[3][2], a3.x, b2.x); fma2(acc[3][3], a3.x, b3.x);
            // second l-pair
            fma2(acc[0][0], a0.y, b0.y); fma2(acc[0][1], a0.y, b1.y);
            fma2(acc[0][2], a0.y, b2.y); fma2(acc[0][3], a0.y, b3.y);
            fma2(acc[1][0], a1.y, b0.y); fma2(acc[1][1], a1.y, b1.y);
            fma2(acc[1][2], a1.y, b2.y); fma2(acc[1][3], a1.y, b3.y);
            fma2(acc[2][0], a2.y, b0.y); fma2(acc[2][1], a2.y, b1.y);
            fma2(acc[2][2], a2.y, b2.y); fma2(acc[2][3], a2.y, b3.y);
            fma2(acc[3][0], a3.y, b0.y); fma2(acc[3][1], a3.y, b1.y);
            fma2(acc[3][2], a3.y, b2.y); fma2(acc[3][3], a3.y, b3.y);
        }

        // channel sums: thread sums quarter-row c = tid>>2, seg (tid&3)*32
        {
            const float* rowp = buf + (tid >> 2) * GPAD + (tid & 3) * 32;
            float s0 = 0.f, s1 = 0.f, s2 = 0.f, s3 = 0.f;
            #pragma unroll
            for (int q = 0; q < 8; q++) {
                float4 v = *(const float4*)&rowp[q * 4];
                s0 += v.x; s1 += v.y; s2 += v.z; s3 += v.w;
            }
            csum += (s0 + s1) + (s2 + s3);
        }
        __syncthreads();
    }

    // epilogue: horizontal pair-sum + partial Gram store
    float* gp = g_gram_part + (size_t)bid * 4096;
    #pragma unroll
    for (int i = 0; i < 4; i++) {
        #pragma unroll
        for (int q = 0; q < 4; q++) {
            float2 p = unpk(acc[i][q]);
            gp[(r + i) * 64 + tx + 16 * q] = p.x + p.y;
        }
    }
    // channel sums: combine the 4 lanes sharing one channel (width-4 shfl)
    csum += __shfl_down_sync(0xffffffffu, csum, 2, 4);
    csum += __shfl_down_sync(0xffffffffu, csum, 1, 4);
    if ((tid & 3) == 0) g_sum_part[bid * 64 + (tid >> 2)] = csum;
}

// ================= Kernel 2: deterministic reduction of partials =================
__global__ __launch_bounds__(256) void reduce_kernel() {
    __shared__ float s[256];
    const int tid = threadIdx.x;
    if (blockIdx.x < 128) {
        const int e = blockIdx.x * 32 + (tid & 31);
        const int ch = tid >> 5;                           // 0..7, 37 partials each
        const float* base = g_gram_part + (size_t)(ch * 37) * 4096 + e;
        float a0 = 0, a1 = 0, a2 = 0, a3 = 0;
        #pragma unroll 1
        for (int q = 0; q < 36; q += 4) {
            a0 += base[(size_t)(q + 0) * 4096];
            a1 += base[(size_t)(q + 1) * 4096];
            a2 += base[(size_t)(q + 2) * 4096];
            a3 += base[(size_t)(q + 3) * 4096];
        }
        a0 += base[(size_t)36 * 4096];
        s[tid] = (a0 + a1) + (a2 + a3);
        __syncthreads();
        if (tid < 32) {
            float r = 0.f;
            #pragma unroll
            for (int ch2 = 0; ch2 < 8; ch2++) r += s[ch2 * 32 + tid];
            g_gram[blockIdx.x * 32 + tid] = r;
        }
    } else {
        const int c = tid & 63, ch = tid >> 6;             // 4 chunks x 74 partials
        const float* base = g_sum_part + (size_t)(ch * 74) * 64 + c;
        float a0 = 0, a1 = 0;
        #pragma unroll 1
        for (int q = 0; q < 74; q += 2) {
            a0 += base[(q + 0) * 64];
            a1 += base[(q + 1) * 64];
        }
        s[tid] = a0 + a1;
        __syncthreads();
        if (tid < 64) {
            float r = (s[tid] + s[64 + tid]) + (s[128 + tid] + s[192 + tid]);
            g_mean[tid] = r * (1.0f / (float)Mm);
        }
    }
}

// ================= Kernel 3: Sigma + Newton-Schulz (single block) =================
// Per iteration: phase A computes U = P*P and V = P*S concurrently (shared A-loads,
// 2x ILP), phase B computes W = U*V with the P-update fused. 2 syncs per iteration.
#define SOLVER_SMEM (4 * 4096 * (int)sizeof(float))

__global__ __launch_bounds__(256) void solver_kernel() {
    extern __shared__ float ssm[];
    float* P = ssm;
    float* S = ssm + 4096;
    float* U = ssm + 8192;
    float* V = ssm + 12288;
    const int tid = threadIdx.x;
    const float inv_m = 1.0f / (float)Mm;

    for (int e = tid; e < 4096; e += 256) {
        int c1 = e >> 6, c2 = e & 63;
        S[e] = g_gram[e] * inv_m - g_mean[c1] * g_mean[c2] + ((c1 == c2) ? EPSV : 0.0f);
    }
    __syncthreads();

    float tr = 0.f;
    #pragma unroll
    for (int c = 0; c < 64; c++) tr += S[c * 65];
    const float rTr = 1.0f / tr;
    __syncthreads();

    for (int e = tid; e < 4096; e += 256) {
        S[e] *= rTr;
        int c1 = e >> 6, c2 = e & 63;
        P[e] = (c1 == c2) ? 1.0f : 0.0f;
    }
    __syncthreads();

    const int ty = tid >> 4, tx = tid & 15;
    const int r = ty * 4, cb = tx * 4;

    #pragma unroll 1
    for (int it = 0; it < 5; it++) {
        // ---- phase A: U = P*P and V = P*S, shared A-loads ----
        unsigned long long aU[4][2] = {}, aV[4][2] = {};
        #pragma unroll
        for (int k4 = 0; k4 < 16; k4++) {
            float4 a0 = *(const float4*)&P[(r + 0) * 64 + k4 * 4];
            float4 a1 = *(const float4*)&P[(r + 1) * 64 + k4 * 4];
            float4 a2 = *(const float4*)&P[(r + 2) * 64 + k4 * 4];
            float4 a3 = *(const float4*)&P[(r + 3) * 64 + k4 * 4];
            #pragma unroll
            for (int kk = 0; kk < 4; kk++) {
                float f0 = kk == 0 ? a0.x : kk == 1 ? a0.y : kk == 2 ? a0.z : a0.w;
                float f1 = kk == 0 ? a1.x : kk == 1 ? a1.y : kk == 2 ? a1.z : a1.w;
                float f2 = kk == 0 ? a2.x : kk == 1 ? a2.y : kk == 2 ? a2.z : a2.w;
                float f3 = kk == 0 ? a3.x : kk == 1 ? a3.y : kk == 2 ? a3.z : a3.w;
                const int k = k4 * 4 + kk;
                ulonglong2 bp = *(const ulonglong2*)&P[k * 64 + cb];
                ulonglong2 bs = *(const ulonglong2*)&S[k * 64 + cb];
                unsigned long long d;
                d = dup2(f0);
                fma2(aU[0][0], d, bp.x); fma2(aU[0][1], d, bp.y);
                fma2(aV[0][0], d, bs.x); fma2(aV[0][1], d, bs.y);
                d = dup2(f1);
                fma2(aU[1][0], d, bp.x); fma2(aU[1][1], d, bp.y);
                fma2(aV[1][0], d, bs.x); fma2(aV[1][1], d, bs.y);
                d = dup2(f2);
                fma2(aU[2][0], d, bp.x); fma2(aU[2][1], d, bp.y);
                fma2(aV[2][0], d, bs.x); fma2(aV[2][1], d, bs.y);
                d = dup2(f3);
                fma2(aU[3][0], d, bp.x); fma2(aU[3][1], d, bp.y);
                fma2(aV[3][0], d, bs.x); fma2(aV[3][1], d, bs.y);
            }
        }
        #pragma unroll
        for (int i = 0; i < 4; i++) {
            float2 u0 = unpk(aU[i][0]), u1 = unpk(aU[i][1]);
            float2 v0 = unpk(aV[i][0]), v1 = unpk(aV[i][1]);
            *(float4*)&U[(r + i) * 64 + cb] = make_float4(u0.x, u0.y, u1.x, u1.y);
            *(float4*)&V[(r + i) * 64 + cb] = make_float4(v0.x, v0.y, v1.x, v1.y);
        }
        __syncthreads();

        // ---- phase B: W = U*V, P = 1.5P - 0.5W fused ----
        unsigned long long aW[4][2] = {};
        #pragma unroll
        for (int k4 = 0; k4 < 16; k4++) {
            float4 a0 = *(const float4*)&U[(r + 0) * 64 + k4 * 4];
            float4 a1 = *(const float4*)&U[(r + 1) * 64 + k4 * 4];
            float4 a2 = *(const float4*)&U[(r + 2) * 64 + k4 * 4];
            float4 a3 = *(const float4*)&U[(r + 3) * 64 + k4 * 4];
            #pragma unroll
            for (int kk = 0; kk < 4; kk++) {
                float f0 = kk == 0 ? a0.x : kk == 1 ? a0.y : kk == 2 ? a0.z : a0.w;
                float f1 = kk == 0 ? a1.x : kk == 1 ? a1.y : kk == 2 ? a1.z : a1.w;
                float f2 = kk == 0 ? a2.x : kk == 1 ? a2.y : kk == 2 ? a2.z : a2.w;
                float f3 = kk == 0 ? a3.x : kk == 1 ? a3.y : kk == 2 ? a3.z : a3.w;
                ulonglong2 bv = *(const ulonglong2*)&V[(k4 * 4 + kk) * 64 + cb];
                unsigned long long d;
                d = dup2(f0); fma2(aW[0][0], d, bv.x); fma2(aW[0][1], d, bv.y);
                d = dup2(f1); fma2(aW[1][0], d, bv.x); fma2(aW[1][1], d, bv.y);
                d = dup2(f2); fma2(aW[2][0], d, bv.x); fma2(aW[2][1], d, bv.y);
                d = dup2(f3); fma2(aW[3][0], d, bv.x); fma2(aW[3][1], d, bv.y);
            }
        }
        #pragma unroll
        for (int i = 0; i < 4; i++) {
            float2 w0 = unpk(aW[i][0]), w1 = unpk(aW[i][1]);
            float* pr = &P[(r + i) * 64 + cb];
            float4 pv = *(float4*)pr;
            *(float4*)pr = make_float4(1.5f * pv.x - 0.5f * w0.x,
                                       1.5f * pv.y - 0.5f * w0.y,
                                       1.5f * pv.z - 0.5f * w1.x,
                                       1.5f * pv.w - 0.5f * w1.y);
        }
        __syncthreads();
    }

    const float sq = sqrtf(rTr);
    for (int e = tid; e < 4096; e += 256) {
        int c = e >> 6, cp = e & 63;
        g_wmT[cp * 64 + c] = P[e] * sq;
    }
    if (tid < 64) {
        float bs = 0.f;
        #pragma unroll 8
        for (int cp = 0; cp < 64; cp++) bs += P[tid * 64 + cp] * g_mean[cp];
        g_bias[tid] = bs * sq;
    }
}

// ================= Kernel 4: apply  Y = wm @ X - bias =================
// Grid 296, cp.async double-buffered 64x128 tiles. PAIR-OVER-ROWS accumulators:
// A pairs (wm[r][k], wm[r+1][k]) are direct 64-bit loads from wmT[k][c]; only the
// 4 x-values need dup2 (8 -> 4 movs per k). Warp w owns rows w*8..+7, lane owns
// cols lane*4..+3.
#define APPLY_SMEM ((4096 + 2 * 8192 + 64) * (int)sizeof(float))

__global__ __launch_bounds__(256, 2) void apply_kernel(const float* __restrict__ X,
                                                       float* __restrict__ Y) {
    extern __shared__ float sm[];
    float* s_w = sm;                     // wmT[k][c]              16 KB
    float* s_x = sm + 4096;              // 2 x [64][128] tiles    64 KB
    float* s_b = sm + 4096 + 16384;      // bias
    const int tid = threadIdx.x;
    const int bid = blockIdx.x;
    const int ts = (bid * NT_A) / NBLK;
    const int te = ((bid + 1) * NT_A) / NBLK;

    #pragma unroll
    for (int itw = 0; itw < 4; itw++) {
        int p = itw * 256 + tid;
        *(float4*)&s_w[p * 4] = *(const float4*)&g_wmT[p * 4];
    }
    if (tid < 64) s_b[tid] = g_bias[tid];

    const uint32_t sx_base = smem_u32(s_x);
    const int c8 = tid >> 5;
    const int j4 = tid & 31;

    {
        int bb = ts >> 6, l = (ts & 63) << 7;
        const float* Xb = X + (size_t)bb * Cc * Lc + l + j4 * 4;
        #pragma unroll
        for (int itc = 0; itc < 8; itc++) {
            int c = itc * 8 + c8;
            cpasync16(sx_base + (uint32_t)(c * 128 + j4 * 4) * 4, Xb + (size_t)c * Lc);
        }
        CP_COMMIT();
    }

    const int w = tid >> 5, lane = tid & 31;
    const int r = w * 8, j0 = lane * 4;

    #pragma unroll 1
    for (int i = ts; i < te; i++) {
        const int cur = (i - ts) & 1;
        if (i + 1 < te) {
            int bb = (i + 1) >> 6, l = ((i + 1) & 63) << 7;
            const float* Xb = X + (size_t)bb * Cc * Lc + l + j4 * 4;
            const uint32_t dst0 = sx_base + (uint32_t)((1 - cur) * 8192) * 4;
            #pragma unroll
            for (int itc = 0; itc < 8; itc++) {
                int c = itc * 8 + c8;
                cpasync16(dst0 + (uint32_t)(c * 128 + j4 * 4) * 4, Xb + (size_t)c * Lc);
            }
            CP_COMMIT();
            CP_WAIT(1);
        } else {
            CP_WAIT(0);
        }
        __syncthreads();

        const float* xb = s_x + cur * 8192;
        unsigned long long acc[4][4];      // acc[p][j]: rows (r+2p, r+2p+1), col j0+j
        #pragma unroll
        for (int p = 0; p < 4; p++) { acc[p][0] = acc[p][1] = acc[p][2] = acc[p][3] = 0ull; }

        #pragma unroll 8
        for (int k = 0; k < 64; k++) {
            ulonglong2 aA = *(const ulonglong2*)&s_w[k * 64 + r];      // (r,r+1),(r+2,r+3)
            ulonglong2 aB = *(const ulonglong2*)&s_w[k * 64 + r + 4];  // (r+4,r+5),(r+6,r+7)
            float4 xv = *(const float4*)&xb[k * 128 + j0];
            unsigned long long d0 = dup2(xv.x), d1 = dup2(xv.y);
            unsigned long long d2 = dup2(xv.z), d3 = dup2(xv.w);
            fma2(acc[0][0], aA.x, d0); fma2(acc[0][1], aA.x, d1);
            fma2(acc[0][2], aA.x, d2); fma2(acc[0][3], aA.x, d3);
            fma2(acc[1][0], aA.y, d0); fma2(acc[1][1], aA.y, d1);
            fma2(acc[1][2], aA.y, d2); fma2(acc[1][3], aA.y, d3);
            fma2(acc[2][0], aB.x, d0); fma2(acc[2][1], aB.x, d1);
            fma2(acc[2][2], aB.x, d2); fma2(acc[2][3], aB.x, d3);
            fma2(acc[3][0], aB.y, d0); fma2(acc[3][1], aB.y, d1);
            fma2(acc[3][2], aB.y, d2); fma2(acc[3][3], aB.y, d3);
        }

        {
            int bb = i >> 6, l = (i & 63) << 7;
            float* Yb = Y + (size_t)bb * Cc * Lc + l + j0;
            #pragma unroll
            for (int p = 0; p < 4; p++) {
                float bb0 = s_b[r + 2 * p], bb1 = s_b[r + 2 * p + 1];
                float2 e0 = unpk(acc[p][0]), e1 = unpk(acc[p][1]);
                float2 e2 = unpk(acc[p][2]), e3 = unpk(acc[p][3]);
                *(float4*)&Yb[(size_t)(r + 2 * p) * Lc] =
                    make_float4(e0.x - bb0, e1.x - bb0, e2.x - bb0, e3.x - bb0);
                *(float4*)&Yb[(size_t)(r + 2 * p + 1) * Lc] =
                    make_float4(e0.y - bb1, e1.y - bb1, e2.y - bb1, e3.y - bb1);
            }
        }
        __syncthreads();
    }
}

// ================= launch =================
extern "C" void kernel_launch(void* const* d_in, const int* in_sizes, int n_in,
                              void* d_out, int out_size) {
    const float* X = (const float*)d_in[0];
    float* Y = (float*)d_out;

    cudaFuncSetAttribute(gram_kernel, cudaFuncAttributeMaxDynamicSharedMemorySize,
                         GRAM_SMEM);
    cudaFuncSetAttribute(apply_kernel, cudaFuncAttributeMaxDynamicSharedMemorySize,
                         APPLY_SMEM);
    cudaFuncSetAttribute(solver_kernel, cudaFuncAttributeMaxDynamicSharedMemorySize,
                         SOLVER_SMEM);

    gram_kernel<<<NBLK, 256, GRAM_SMEM>>>(X);
    reduce_kernel<<<129, 256>>>();
    solver_kernel<<<1, 256, SOLVER_SMEM>>>();
    apply_kernel<<<NBLK, 256, APPLY_SMEM>>>(X, Y);
}